// round 8
// baseline (speedup 1.0000x reference)
#include <cuda_runtime.h>

// x: (32, 256, 256, 16) float32, contiguous.
// p[h][w] = mean over b (32) and c (16) of x[b][h][w][c]   (512-way reduction)
// out = (p >= ALPHA) ? (ALPHA/p)*x : beta*x + (1-beta),  beta = (1-ALPHA)/(1-p)
// Both branches affine in x: out = a*x + c, per-(h,w) constants.
//
// PERSISTENT warp-autonomous version: grid = 592 blocks (148 SMs x 4 = exactly
// one wave), each block grid-strides over the 4096 (h, w-chunk) tiles. No wave
// transitions; blocks desynchronize after tile 0 so some warps are always in
// their load phase while others reduce/store -> DRAM stays fed.
//
// Per tile: one warp owns 2 w-positions (2w x 16c x 32b = 256 float4).
// Lane l: pos4 = l & 7 (float4 slot in the 8-f4 contiguous per-batch slice),
//         bgrp = l >> 3 (batches bgrp*8 .. +7, 8 float4 held in registers).
// Reduce: shfl_xor 1,2 (channel lanes) + 8,16 (batch groups). No smem, no bar.

#define ALPHA_F 0.25f

static constexpr int BSTRIDE4  = 256 * 256 * 16 / 4;  // batch stride in float4
static constexpr int NUM_TILES = 4096;                // 256 h x 16 w-chunks
static constexpr int GRID      = 592;                 // 148 SMs x 4 CTAs

__global__ void __launch_bounds__(256)
rescale_prob_mask_kernel(const float* __restrict__ x, float* __restrict__ out) {
    const int t    = threadIdx.x;
    const int lane = t & 31;
    const int wid  = t >> 5;          // warp within block: 0..7 -> w pair

    const int pos4 = lane & 7;        // float4 slot in the 8-f4 contiguous slice
    const int bgrp = lane >> 3;       // 0..3, 8 batches each

    const float4* __restrict__ x4 = (const float4*)x;
    float4*       __restrict__ o4 = (float4*)out;

    const size_t lane_off = (size_t)pos4 + (size_t)(bgrp * 8) * (size_t)BSTRIDE4
                          + (size_t)wid * 8;

    for (int tile = blockIdx.x; tile < NUM_TILES; tile += GRID) {
        const int h  = tile >> 4;     // 0..255
        const int wq = tile & 15;     // 16-w chunk; warp owns 2 of the 16 w

        const size_t idx0 = (size_t)h * 1024 + (size_t)wq * 64 + lane_off;

        // ---- Load 8 float4 into registers (streaming: no reuse) ----
        float4 v[8];
#pragma unroll
        for (int j = 0; j < 8; j++)
            v[j] = __ldcs(&x4[idx0 + (size_t)j * BSTRIDE4]);

        // ---- Warp-local reduction: 512 values per w ----
        float s = 0.0f;
#pragma unroll
        for (int j = 0; j < 8; j++)
            s += (v[j].x + v[j].y) + (v[j].z + v[j].w);

        s += __shfl_xor_sync(0xffffffffu, s, 1);   // channel lanes
        s += __shfl_xor_sync(0xffffffffu, s, 2);
        s += __shfl_xor_sync(0xffffffffu, s, 8);   // batch groups
        s += __shfl_xor_sync(0xffffffffu, s, 16);

        const float p = s * (1.0f / 512.0f);
        float a, c;
        if (p >= ALPHA_F) {
            a = ALPHA_F / p;
            c = 0.0f;
        } else {
            const float beta = (1.0f - ALPHA_F) / (1.0f - p);
            a = beta;
            c = 1.0f - beta;
        }

        // ---- Fused affine on held registers, streaming store ----
#pragma unroll
        for (int j = 0; j < 8; j++) {
            float4 r;
            r.x = fmaf(a, v[j].x, c);
            r.y = fmaf(a, v[j].y, c);
            r.z = fmaf(a, v[j].z, c);
            r.w = fmaf(a, v[j].w, c);
            __stcs(&o4[idx0 + (size_t)j * BSTRIDE4], r);
        }
    }
}

extern "C" void kernel_launch(void* const* d_in, const int* in_sizes, int n_in,
                              void* d_out, int out_size) {
    const float* x   = (const float*)d_in[0];
    float*       out = (float*)d_out;
    rescale_prob_mask_kernel<<<GRID, 256>>>(x, out);
}

// round 12
// speedup vs baseline: 1.0583x; 1.0583x over previous
#include <cuda_runtime.h>

// x: (32, 256, 256, 16) float32, contiguous.
// p[h][w] = mean over b (32) and c (16) of x[b][h][w][c]   (512-way reduction)
// out = (p >= ALPHA) ? (ALPHA/p)*x : beta*x + (1-beta),  beta = (1-ALPHA)/(1-p)
// Both branches affine in x: out = a*x + c, per-(h,w) constants.
//
// Wide-tile register-staged version (evolution of the fastest R3 kernel):
// one block = 512 threads owns a (h, w-eighth) tile: 32 w x 16 c x 32 b
// = 64 KiB = 4096 float4. Per batch the block reads 2 KiB CONTIGUOUS
// (matches the 2 KiB HBM page grain -> better row locality than 1 KiB).
// Thread t: pos4 = t & 127 (float4 slot in the 128-f4 contiguous slice,
//           w_local = pos4>>2), bgrp = t >> 7 (batches bgrp*8 .. +7).
// Each thread holds its 8 float4 in registers across the reduction
// (no DRAM re-read). ONE barrier: partials -> smem -> sync -> every
// thread redundantly folds the 4 partials for its own w (cheap: 3 adds
// + 1 div), then fma + store from registers.

#define ALPHA_F 0.25f

static constexpr int BSTRIDE4 = 256 * 256 * 16 / 4;  // batch stride in float4 = 262144

__global__ void __launch_bounds__(512)
rescale_prob_mask_kernel(const float* __restrict__ x, float* __restrict__ out) {
    __shared__ float s_part[4][32];   // [batch-group][w_local]

    const int t    = threadIdx.x;
    const int pos4 = t & 127;         // float4 slot within the per-batch slice
    const int bgrp = t >> 7;          // 0..3 -> 8 batches each
    const int w    = pos4 >> 2;       // 0..31 local w

    const int h  = blockIdx.x >> 3;   // 0..255
    const int wq = blockIdx.x & 7;    // 0..7 (32-wide w chunk)

    // float4 offset of this block's slice within one batch image (1024 f4/row)
    const size_t base4 = (size_t)h * 1024 + (size_t)wq * 128;
    const size_t idx0  = base4 + (size_t)pos4
                       + (size_t)(bgrp * 8) * (size_t)BSTRIDE4;

    const float4* __restrict__ x4 = (const float4*)x;
    float4*       __restrict__ o4 = (float4*)out;

    // ---- Load 8 float4 into registers (8 independent LDG.128, high MLP) ----
    float4 v[8];
#pragma unroll
    for (int j = 0; j < 8; j++)
        v[j] = x4[idx0 + (size_t)j * BSTRIDE4];

    // ---- Reduce: each thread sums its 32 values ----
    float s = 0.0f;
#pragma unroll
    for (int j = 0; j < 8; j++)
        s += (v[j].x + v[j].y) + (v[j].z + v[j].w);

    // combine the 4 channel lanes sharing one w (lanes 4k..4k+3)
    s += __shfl_xor_sync(0xffffffffu, s, 1);
    s += __shfl_xor_sync(0xffffffffu, s, 2);

    if ((t & 3) == 0)
        s_part[bgrp][w] = s;          // per (batch-group, w) partial: 16c x 8b
    __syncthreads();                  // the ONLY barrier

    // every thread folds the 4 batch-group partials for its own w
    const float p = (s_part[0][w] + s_part[1][w] + s_part[2][w] + s_part[3][w])
                    * (1.0f / 512.0f);
    float a, c;
    if (p >= ALPHA_F) {
        a = ALPHA_F / p;
        c = 0.0f;
    } else {
        const float beta = (1.0f - ALPHA_F) / (1.0f - p);
        a = beta;
        c = 1.0f - beta;
    }

    // ---- Fused affine on held registers, store ----
#pragma unroll
    for (int j = 0; j < 8; j++) {
        float4 r;
        r.x = fmaf(a, v[j].x, c);
        r.y = fmaf(a, v[j].y, c);
        r.z = fmaf(a, v[j].z, c);
        r.w = fmaf(a, v[j].w, c);
        o4[idx0 + (size_t)j * BSTRIDE4] = r;
    }
}

extern "C" void kernel_launch(void* const* d_in, const int* in_sizes, int n_in,
                              void* d_out, int out_size) {
    const float* x   = (const float*)d_in[0];
    float*       out = (float*)d_out;
    // 256 h-rows x 8 w-chunks = 2048 blocks of 512 threads
    rescale_prob_mask_kernel<<<2048, 512>>>(x, out);
}